// round 4
// baseline (speedup 1.0000x reference)
#include <cuda_runtime.h>
#include <math.h>

// Problem dimensions (fixed)
#define B_   128
#define T_   32
#define DIN  1024
#define H_   1024
#define V_   2048
#define A_   512
#define NROI 64

// ---------------- scratch (static device globals; no allocations) ----------
__device__ float g_mean[B_ * V_];                // mean visual     [128,2048]
__device__ float g_h[B_ * H_];                   // hidden state    [128,1024]
__device__ float g_c[B_ * H_];                   // cell state      [128,1024]
__device__ float g_va[(size_t)B_ * NROI * A_];   // visual attn enc [128,64,512]
__device__ float g_pi[(size_t)B_ * T_ * 6 * H_]; // x projections   [128,32,6144]
__device__ float g_he[B_ * A_];                  // h attn enc, K-half 0
__device__ float g_he2[B_ * A_];                 // h attn enc, K-half 1
__device__ float g_ctx[B_ * V_];                 // context         [128,2048]
__device__ float g_ps[B_ * 5 * H_];              // state proj, K-half 0
__device__ float g_ps2[B_ * 5 * H_];             // state proj, K-half 1
__device__ float g_pa[B_ * 5 * H_];              // attn proj, K-half 0
__device__ float g_pa2[B_ * 5 * H_];             // attn proj, K-half 1
__device__ float g_zero[64];                     // zero bias (bss, zero-init)

__device__ __forceinline__ float sigmoidf(float x) { return 1.0f / (1.0f + expf(-x)); }

// packed f32x2 FMA: d.lo += a.lo*b.lo ; d.hi += a.hi*b.hi  (full fp32, rn)
#define FMA2(d, a, b) asm("fma.rn.f32x2 %0, %1, %2, %0;" : "+l"(d) : "l"(a), "l"(b))

__device__ __forceinline__ float2 unpk(unsigned long long v) {
    float2 f;
    asm("mov.b64 {%0, %1}, %2;" : "=f"(f.x), "=f"(f.y) : "l"(v));
    return f;
}

// ---------------------------------------------------------------------------
// mean_vis[b,v] = sum_{n<L} visual[b,n,v] / L
// ---------------------------------------------------------------------------
__global__ void mean_vis_kernel(const float* __restrict__ visual,
                                const int* __restrict__ ls_rois)
{
    int b = blockIdx.x;
    int L = ls_rois[b];
    const float4* vb = (const float4*)(visual + (size_t)b * NROI * V_);
    float invL = 1.0f / (float)L;
    float4* out = (float4*)(g_mean + b * V_);
    for (int v4 = threadIdx.x; v4 < V_ / 4; v4 += blockDim.x) {
        float4 s = make_float4(0.f, 0.f, 0.f, 0.f);
#pragma unroll 4
        for (int n = 0; n < NROI; n++) {
            if (n < L) {
                float4 x = vb[(size_t)n * (V_ / 4) + v4];
                s.x += x.x; s.y += x.y; s.z += x.z; s.w += x.w;
            }
        }
        s.x *= invL; s.y *= invL; s.z *= invL; s.w *= invL;
        out[v4] = s;
    }
}

// ---------------------------------------------------------------------------
// Generic NT GEMM with bias, FFMA2 (f32x2) path.
// BM=BN=64, BK=16, 256 threads, 4x4 per thread (M-paired accumulators).
// B tile stored as duplicated float2 pairs so FFMA2 needs no packing ops.
// ---------------------------------------------------------------------------
__global__ __launch_bounds__(256)
void gemm_nt_bias(const float* __restrict__ A, const float* __restrict__ W,
                  const float* __restrict__ bias, float* __restrict__ C,
                  int M, int N, int K)
{
    __shared__ float  As[16][64];
    __shared__ float2 Bs[16][64];     // each entry = (w, w)

    const int bm = blockIdx.y * 64;
    const int bn = blockIdx.x * 64;
    const int tid = threadIdx.x;
    const int tr = tid >> 4;           // 0..15 (4-row group)
    const int tc = tid & 15;           // 0..15 (4-col group)
    const int lr = tid >> 2;           // 0..63
    const int lc = (tid & 3) << 2;     // 0,4,8,12

    const float* Ap = A + (size_t)(bm + lr) * K + lc;
    const float* Wp = W + (size_t)(bn + lr) * K + lc;

    unsigned long long acc[2][4];
#pragma unroll
    for (int p = 0; p < 2; p++)
#pragma unroll
        for (int j = 0; j < 4; j++) acc[p][j] = 0ull;

    float4 av = *(const float4*)(Ap);
    float4 wv = *(const float4*)(Wp);

    for (int k0 = 0; k0 < K; k0 += 16) {
        As[lc + 0][lr] = av.x; As[lc + 1][lr] = av.y;
        As[lc + 2][lr] = av.z; As[lc + 3][lr] = av.w;
        Bs[lc + 0][lr] = make_float2(wv.x, wv.x);
        Bs[lc + 1][lr] = make_float2(wv.y, wv.y);
        Bs[lc + 2][lr] = make_float2(wv.z, wv.z);
        Bs[lc + 3][lr] = make_float2(wv.w, wv.w);
        __syncthreads();
        if (k0 + 16 < K) {
            av = *(const float4*)(Ap + k0 + 16);
            wv = *(const float4*)(Wp + k0 + 16);
        }
#pragma unroll
        for (int kk = 0; kk < 16; kk++) {
            ulonglong2 ap = *(const ulonglong2*)&As[kk][tr << 2];
            ulonglong2 b0 = *(const ulonglong2*)&Bs[kk][tc << 2];
            ulonglong2 b1 = *(const ulonglong2*)&Bs[kk][(tc << 2) + 2];
            FMA2(acc[0][0], ap.x, b0.x); FMA2(acc[0][1], ap.x, b0.y);
            FMA2(acc[0][2], ap.x, b1.x); FMA2(acc[0][3], ap.x, b1.y);
            FMA2(acc[1][0], ap.y, b0.x); FMA2(acc[1][1], ap.y, b0.y);
            FMA2(acc[1][2], ap.y, b1.x); FMA2(acc[1][3], ap.y, b1.y);
        }
        __syncthreads();
    }

    float4 bv4 = *(const float4*)(bias + bn + (tc << 2));
#pragma unroll
    for (int p = 0; p < 2; p++) {
        float2 v0 = unpk(acc[p][0]), v1 = unpk(acc[p][1]);
        float2 v2 = unpk(acc[p][2]), v3 = unpk(acc[p][3]);
        int r0 = bm + (tr << 2) + 2 * p;
        float4 o0 = make_float4(v0.x + bv4.x, v1.x + bv4.y, v2.x + bv4.z, v3.x + bv4.w);
        float4 o1 = make_float4(v0.y + bv4.x, v1.y + bv4.y, v2.y + bv4.z, v3.y + bv4.w);
        *(float4*)(C + (size_t)r0 * N + bn + (tc << 2)) = o0;
        *(float4*)(C + (size_t)(r0 + 1) * N + bn + (tc << 2)) = o1;
    }
}

// ---------------------------------------------------------------------------
// M=128 step-GEMM core, FFMA2 path, strided A/W (for split-K).
// One block computes C[0:128, 0:32] for the given K range.
// ---------------------------------------------------------------------------
__device__ __forceinline__
void gemm_m128_f2_core(float As[16][128], float2 Bs[16][32],
                       const float* __restrict__ A, int lda,
                       const float* __restrict__ Wn, int ldw,
                       const float* __restrict__ biasn, float* __restrict__ Cn,
                       int ldc, int Klen)
{
    const int tid = threadIdx.x;
    const int lm  = tid & 127;            // A-load row
    const int lkh = (tid >> 7) << 3;      // A-load k base: 0 or 8
    const int bn  = tid >> 2;             // W-load row (tid<128 -> 0..31)
    const int bk  = (tid & 3) << 2;       // W-load k base
    const int ty  = tid >> 3;             // 0..31 (4-row group)
    const int tx  = tid & 7;              // 0..7  (4-col group)

    const float* Ap = A + (size_t)lm * lda + lkh;
    const float* Wp = Wn + (size_t)bn * ldw + bk;

    unsigned long long acc[2][4];
#pragma unroll
    for (int p = 0; p < 2; p++)
#pragma unroll
        for (int j = 0; j < 4; j++) acc[p][j] = 0ull;

    float4 a0 = *(const float4*)(Ap);
    float4 a1 = *(const float4*)(Ap + 4);
    float4 w  = make_float4(0.f, 0.f, 0.f, 0.f);
    if (tid < 128) w = *(const float4*)(Wp);

    for (int k0 = 0; k0 < Klen; k0 += 16) {
        As[lkh + 0][lm] = a0.x; As[lkh + 1][lm] = a0.y;
        As[lkh + 2][lm] = a0.z; As[lkh + 3][lm] = a0.w;
        As[lkh + 4][lm] = a1.x; As[lkh + 5][lm] = a1.y;
        As[lkh + 6][lm] = a1.z; As[lkh + 7][lm] = a1.w;
        if (tid < 128) {
            Bs[bk + 0][bn] = make_float2(w.x, w.x);
            Bs[bk + 1][bn] = make_float2(w.y, w.y);
            Bs[bk + 2][bn] = make_float2(w.z, w.z);
            Bs[bk + 3][bn] = make_float2(w.w, w.w);
        }
        __syncthreads();
        if (k0 + 16 < Klen) {
            a0 = *(const float4*)(Ap + k0 + 16);
            a1 = *(const float4*)(Ap + k0 + 20);
            if (tid < 128) w = *(const float4*)(Wp + k0 + 16);
        }
#pragma unroll
        for (int kk = 0; kk < 16; kk++) {
            ulonglong2 ap = *(const ulonglong2*)&As[kk][ty << 2];
            ulonglong2 b0 = *(const ulonglong2*)&Bs[kk][tx << 2];
            ulonglong2 b1 = *(const ulonglong2*)&Bs[kk][(tx << 2) + 2];
            FMA2(acc[0][0], ap.x, b0.x); FMA2(acc[0][1], ap.x, b0.y);
            FMA2(acc[0][2], ap.x, b1.x); FMA2(acc[0][3], ap.x, b1.y);
            FMA2(acc[1][0], ap.y, b0.x); FMA2(acc[1][1], ap.y, b0.y);
            FMA2(acc[1][2], ap.y, b1.x); FMA2(acc[1][3], ap.y, b1.y);
        }
        __syncthreads();
    }

    float4 bv = *(const float4*)(biasn + (tx << 2));
#pragma unroll
    for (int p = 0; p < 2; p++) {
        float2 v0 = unpk(acc[p][0]), v1 = unpk(acc[p][1]);
        float2 v2 = unpk(acc[p][2]), v3 = unpk(acc[p][3]);
        int r0 = (ty << 2) + 2 * p;
        float4 o0 = make_float4(v0.x + bv.x, v1.x + bv.y, v2.x + bv.z, v3.x + bv.w);
        float4 o1 = make_float4(v0.y + bv.x, v1.y + bv.y, v2.y + bv.z, v3.y + bv.w);
        *(float4*)(Cn + (size_t)r0 * ldc + (tx << 2)) = o0;
        *(float4*)(Cn + (size_t)(r0 + 1) * ldc + (tx << 2)) = o1;
    }
}

// step1: [ps | he] = h @ [Ws ; Wh]^T + bias, split-K x2.  grid = 352 blocks.
__global__ __launch_bounds__(256, 2)
void step1_kernel(const float* __restrict__ Ws, const float* __restrict__ bs,
                  const float* __restrict__ Wh, const float* __restrict__ bh)
{
    __shared__ float  As[16][128];
    __shared__ float2 Bs[16][32];
    const int KH = H_ / 2;                        // 512
    int id = blockIdx.x;
    int half = (id >= 176) ? 1 : 0;
    int n0 = (id - half * 176) << 5;
    const float* Ab = g_h + half * KH;
    if (n0 < 5 * H_) {
        gemm_m128_f2_core(As, Bs, Ab, H_,
                          Ws + (size_t)n0 * H_ + half * KH, H_,
                          half ? g_zero : (bs + n0),
                          (half ? g_ps2 : g_ps) + n0, 5 * H_, KH);
    } else {
        int m = n0 - 5 * H_;
        gemm_m128_f2_core(As, Bs, Ab, H_,
                          Wh + (size_t)m * H_ + half * KH, H_,
                          half ? g_zero : (bh + m),
                          (half ? g_he2 : g_he) + m, A_, KH);
    }
}

// step2: pa = ctx @ Wa^T + ba, split-K x2.  grid = 320 blocks.
__global__ __launch_bounds__(256, 2)
void step2_kernel(const float* __restrict__ Wa, const float* __restrict__ ba)
{
    __shared__ float  As[16][128];
    __shared__ float2 Bs[16][32];
    const int KH = V_ / 2;                        // 1024
    int id = blockIdx.x;
    int half = (id >= 160) ? 1 : 0;
    int n0 = (id - half * 160) << 5;
    gemm_m128_f2_core(As, Bs, g_ctx + half * KH, V_,
                      Wa + (size_t)n0 * V_ + half * KH, V_,
                      half ? g_zero : (ba + n0),
                      (half ? g_pa2 : g_pa) + n0, 5 * H_, KH);
}

// ---------------------------------------------------------------------------
// Attention: logits -> masked softmax -> ctx. One block per batch element.
// ---------------------------------------------------------------------------
__global__ __launch_bounds__(256)
void attn_kernel(const float* __restrict__ visual,
                 const float* __restrict__ Wp, const float* __restrict__ bp,
                 const int* __restrict__ ls_rois)
{
    int b = blockIdx.x;
    int tid = threadIdx.x;
    int warp = tid >> 5, lane = tid & 31;

    __shared__ float he_s[A_];
    __shared__ float wp_s[A_];
    __shared__ float att[NROI];

    if (tid < 128) {
        float4 h0 = ((const float4*)(g_he + b * A_))[tid];
        float4 h1 = ((const float4*)(g_he2 + b * A_))[tid];
        ((float4*)he_s)[tid] = make_float4(h0.x + h1.x, h0.y + h1.y,
                                           h0.z + h1.z, h0.w + h1.w);
        ((float4*)wp_s)[tid] = ((const float4*)Wp)[tid];
    }
    __syncthreads();

    int L = ls_rois[b];

    for (int n = warp; n < NROI; n += 8) {
        float s = 0.0f;
        if (n < L) {
            const float4* vrow = (const float4*)(g_va + ((size_t)b * NROI + n) * A_);
            const float4* he4 = (const float4*)he_s;
            const float4* wp4 = (const float4*)wp_s;
#pragma unroll
            for (int a4 = lane; a4 < A_ / 4; a4 += 32) {
                float4 v = vrow[a4];
                float4 h = he4[a4];
                float4 p = wp4[a4];
                s += p.x * fmaxf(v.x + h.x, 0.0f);
                s += p.y * fmaxf(v.y + h.y, 0.0f);
                s += p.z * fmaxf(v.z + h.z, 0.0f);
                s += p.w * fmaxf(v.w + h.w, 0.0f);
            }
        }
#pragma unroll
        for (int o = 16; o; o >>= 1) s += __shfl_xor_sync(0xffffffffu, s, o);
        if (lane == 0) att[n] = s + bp[0];
    }
    __syncthreads();

    if (tid == 0) {
        float mx = -3.0e38f;
        for (int n = 0; n < L; n++) mx = fmaxf(mx, att[n]);
        float den = 0.0f;
        for (int n = 0; n < L; n++) { float e = expf(att[n] - mx); att[n] = e; den += e; }
        float inv = 1.0f / den;
        for (int n = 0; n < L; n++) att[n] *= inv;
        for (int n = L; n < NROI; n++) att[n] = 0.0f;
    }
    __syncthreads();

    const float4* vb4 = (const float4*)(visual + (size_t)b * NROI * V_);
    float4* ctx4 = (float4*)(g_ctx + b * V_);
#pragma unroll
    for (int v4 = tid; v4 < V_ / 4; v4 += 256) {
        float4 s = make_float4(0.f, 0.f, 0.f, 0.f);
#pragma unroll 8
        for (int n = 0; n < NROI; n++) {
            float a = att[n];
            float4 x = vb4[(size_t)n * (V_ / 4) + v4];
            s.x += a * x.x; s.y += a * x.y; s.z += a * x.z; s.w += a * x.w;
        }
        ctx4[v4] = s;
    }
}

// ---------------------------------------------------------------------------
// LSTM gates + highway + state update + output projection for step t.
// ---------------------------------------------------------------------------
__global__ __launch_bounds__(256)
void gate_kernel(const float* __restrict__ Wo, const float* __restrict__ bo,
                 const int* __restrict__ seq_lens, float* __restrict__ y, int t)
{
    const int HQ = H_ / 4;   // 256
    int b = blockIdx.x;
    int tid = threadIdx.x;
    bool valid = (t < seq_lens[b]);

    const float4* pi = (const float4*)(g_pi + ((size_t)b * T_ + t) * (6 * H_));
    const float4* ps = (const float4*)(g_ps + (size_t)b * (5 * H_));
    const float4* ps2 = (const float4*)(g_ps2 + (size_t)b * (5 * H_));
    const float4* pa = (const float4*)(g_pa + (size_t)b * (5 * H_));
    const float4* pa2 = (const float4*)(g_pa2 + (size_t)b * (5 * H_));
    float4* h4 = (float4*)(g_h + b * H_);
    float4* c4 = (float4*)(g_c + b * H_);

    float g[5][4];    // summed gate pre-activations 0..4
#pragma unroll
    for (int kgate = 0; kgate < 5; kgate++) {
        float4 a = pi[kgate * HQ + tid];
        float4 q0 = ps[kgate * HQ + tid];
        float4 q1 = ps2[kgate * HQ + tid];
        float4 r0 = pa[kgate * HQ + tid];
        float4 r1 = pa2[kgate * HQ + tid];
        g[kgate][0] = a.x + q0.x + q1.x + r0.x + r1.x;
        g[kgate][1] = a.y + q0.y + q1.y + r0.y + r1.y;
        g[kgate][2] = a.z + q0.z + q1.z + r0.z + r1.z;
        g[kgate][3] = a.w + q0.w + q1.w + r0.w + r1.w;
    }
    float4 s5 = pi[5 * HQ + tid];
    float pi5[4] = {s5.x, s5.y, s5.z, s5.w};
    float4 cv = c4[tid];
    float cc[4] = {cv.x, cv.y, cv.z, cv.w};
    float4 wo = ((const float4*)Wo)[tid];
    float wof[4] = {wo.x, wo.y, wo.z, wo.w};

    float out[4], mem[4], part = 0.0f;
#pragma unroll
    for (int e = 0; e < 4; e++) {
        float ig = sigmoidf(g[0][e]);
        float fg = sigmoidf(g[1][e]);
        float mi = tanhf(g[2][e]);
        float og = sigmoidf(g[3][e]);
        float m  = ig * mi + fg * cc[e];
        float o  = og * tanhf(m);
        float hw = sigmoidf(g[4][e]);
        out[e] = hw * o + (1.0f - hw) * pi5[e];
        mem[e] = m;
        part += out[e] * wof[e];
    }

    if (valid) {
        h4[tid] = make_float4(out[0], out[1], out[2], out[3]);
        c4[tid] = make_float4(mem[0], mem[1], mem[2], mem[3]);
    }

#pragma unroll
    for (int o = 16; o; o >>= 1) part += __shfl_xor_sync(0xffffffffu, part, o);
    __shared__ float red[8];
    if ((tid & 31) == 0) red[tid >> 5] = part;
    __syncthreads();
    if (tid == 0) {
        float s = 0.0f;
#pragma unroll
        for (int w = 0; w < 8; w++) s += red[w];
        y[b * T_ + t] = valid ? (s + bo[0]) : 0.0f;
    }
}

// ---------------------------------------------------------------------------
extern "C" void kernel_launch(void* const* d_in, const int* in_sizes, int n_in,
                              void* d_out, int out_size)
{
    const float* x      = (const float*)d_in[0];
    const float* visual = (const float*)d_in[1];
    const float* Wi     = (const float*)d_in[2];
    const float* bi     = (const float*)d_in[3];
    const float* Ws     = (const float*)d_in[4];
    const float* bs     = (const float*)d_in[5];
    const float* Wa     = (const float*)d_in[6];
    const float* ba     = (const float*)d_in[7];
    const float* Wv     = (const float*)d_in[8];
    const float* bv     = (const float*)d_in[9];
    const float* Wh     = (const float*)d_in[10];
    const float* bh     = (const float*)d_in[11];
    const float* Wp     = (const float*)d_in[12];
    const float* bp     = (const float*)d_in[13];
    const float* W0h    = (const float*)d_in[14];
    const float* b0h    = (const float*)d_in[15];
    const float* W0c    = (const float*)d_in[16];
    const float* b0c    = (const float*)d_in[17];
    const float* Wo     = (const float*)d_in[18];
    const float* bo     = (const float*)d_in[19];
    const int* ls_rois  = (const int*)d_in[20];
    const int* seq_lens = (const int*)d_in[21];
    float* y = (float*)d_out;

    float *p_mean, *p_h, *p_c, *p_va, *p_pi;
    cudaGetSymbolAddress((void**)&p_mean, g_mean);
    cudaGetSymbolAddress((void**)&p_h,    g_h);
    cudaGetSymbolAddress((void**)&p_c,    g_c);
    cudaGetSymbolAddress((void**)&p_va,   g_va);
    cudaGetSymbolAddress((void**)&p_pi,   g_pi);

    // ---- loop-invariant precompute ----
    mean_vis_kernel<<<B_, 256>>>(visual, ls_rois);
    gemm_nt_bias<<<dim3(H_ / 64, B_ / 64), 256>>>(p_mean, W0h, b0h, p_h, B_, H_, V_);
    gemm_nt_bias<<<dim3(H_ / 64, B_ / 64), 256>>>(p_mean, W0c, b0c, p_c, B_, H_, V_);
    gemm_nt_bias<<<dim3(A_ / 64, (B_ * NROI) / 64), 256>>>(visual, Wv, bv, p_va,
                                                           B_ * NROI, A_, V_);
    gemm_nt_bias<<<dim3((6 * H_) / 64, (B_ * T_) / 64), 256>>>(x, Wi, bi, p_pi,
                                                               B_ * T_, 6 * H_, DIN);

    // ---- recurrent steps: 4 launches/step ----
    for (int t = 0; t < T_; t++) {
        step1_kernel<<<352, 256>>>(Ws, bs, Wh, bh);     // ps + he (split-K x2)
        attn_kernel<<<B_, 256>>>(visual, Wp, bp, ls_rois);
        step2_kernel<<<320, 256>>>(Wa, ba);             // pa (split-K x2)
        gate_kernel<<<B_, 256>>>(Wo, bo, seq_lens, y, t);
    }
}

// round 5
// speedup vs baseline: 1.9938x; 1.9938x over previous
#include <cuda_runtime.h>
#include <math.h>

// Problem dimensions (fixed)
#define B_   128
#define T_   32
#define DIN  1024
#define H_   1024
#define V_   2048
#define A_   512
#define NROI 64

// ---------------- scratch (static device globals; no allocations) ----------
__device__ float g_mean[B_ * V_];                // mean visual     [128,2048]
__device__ float g_h[B_ * H_];                   // hidden state    [128,1024]
__device__ float g_c[B_ * H_];                   // cell state      [128,1024]
__device__ float g_va[(size_t)B_ * NROI * A_];   // visual attn enc [128,64,512]
__device__ float g_pi[(size_t)B_ * T_ * 6 * H_]; // x projections   [128,32,6144]
__device__ float g_he[B_ * A_];                  // h attn enc, K-half 0
__device__ float g_he2[B_ * A_];                 // h attn enc, K-half 1
__device__ float g_ctx[B_ * V_];                 // context         [128,2048]
__device__ float g_ps[B_ * 5 * H_];              // state proj, K-half 0
__device__ float g_ps2[B_ * 5 * H_];             // state proj, K-half 1
__device__ float g_pa[B_ * 5 * H_];              // attn proj, K-half 0
__device__ float g_pa2[B_ * 5 * H_];             // attn proj, K-half 1
__device__ float g_zero[64];                     // zero bias (bss, zero-init)

__device__ __forceinline__ float sigmoidf(float x) { return 1.0f / (1.0f + expf(-x)); }

// ---------------------------------------------------------------------------
// mean_vis[b,v] = sum_{n<L} visual[b,n,v] / L
// ---------------------------------------------------------------------------
__global__ void mean_vis_kernel(const float* __restrict__ visual,
                                const int* __restrict__ ls_rois)
{
    int b = blockIdx.x;
    int L = ls_rois[b];
    const float4* vb = (const float4*)(visual + (size_t)b * NROI * V_);
    float invL = 1.0f / (float)L;
    float4* out = (float4*)(g_mean + b * V_);
    for (int v4 = threadIdx.x; v4 < V_ / 4; v4 += blockDim.x) {
        float4 s = make_float4(0.f, 0.f, 0.f, 0.f);
#pragma unroll 4
        for (int n = 0; n < NROI; n++) {
            if (n < L) {
                float4 x = vb[(size_t)n * (V_ / 4) + v4];
                s.x += x.x; s.y += x.y; s.z += x.z; s.w += x.w;
            }
        }
        s.x *= invL; s.y *= invL; s.z *= invL; s.w *= invL;
        out[v4] = s;
    }
}

// ---------------------------------------------------------------------------
// Generic NT GEMM with bias (precompute path), register-prefetch pipelined,
// SCALAR FFMA (measured ~88% of fp32 scalar peak).
// BM=BN=64, BK=16, 256 threads, 4x4 per thread.
// ---------------------------------------------------------------------------
__global__ __launch_bounds__(256)
void gemm_nt_bias(const float* __restrict__ A, const float* __restrict__ W,
                  const float* __restrict__ bias, float* __restrict__ C,
                  int M, int N, int K)
{
    __shared__ float As[16][64];
    __shared__ float Bs[16][64];

    const int bm = blockIdx.y * 64;
    const int bn = blockIdx.x * 64;
    const int tid = threadIdx.x;
    const int tr = tid >> 4;
    const int tc = tid & 15;
    const int lr = tid >> 2;
    const int lc = (tid & 3) << 2;

    const float* Ap = A + (size_t)(bm + lr) * K + lc;
    const float* Wp = W + (size_t)(bn + lr) * K + lc;

    float acc[4][4];
#pragma unroll
    for (int i = 0; i < 4; i++)
#pragma unroll
        for (int j = 0; j < 4; j++) acc[i][j] = 0.0f;

    float4 av = *(const float4*)(Ap);
    float4 wv = *(const float4*)(Wp);

    for (int k0 = 0; k0 < K; k0 += 16) {
        As[lc + 0][lr] = av.x; As[lc + 1][lr] = av.y;
        As[lc + 2][lr] = av.z; As[lc + 3][lr] = av.w;
        Bs[lc + 0][lr] = wv.x; Bs[lc + 1][lr] = wv.y;
        Bs[lc + 2][lr] = wv.z; Bs[lc + 3][lr] = wv.w;
        __syncthreads();
        if (k0 + 16 < K) {
            av = *(const float4*)(Ap + k0 + 16);
            wv = *(const float4*)(Wp + k0 + 16);
        }
#pragma unroll
        for (int kk = 0; kk < 16; kk++) {
            float4 a = *(const float4*)&As[kk][tr << 2];
            float4 w = *(const float4*)&Bs[kk][tc << 2];
            acc[0][0] += a.x * w.x; acc[0][1] += a.x * w.y; acc[0][2] += a.x * w.z; acc[0][3] += a.x * w.w;
            acc[1][0] += a.y * w.x; acc[1][1] += a.y * w.y; acc[1][2] += a.y * w.z; acc[1][3] += a.y * w.w;
            acc[2][0] += a.z * w.x; acc[2][1] += a.z * w.y; acc[2][2] += a.z * w.z; acc[2][3] += a.z * w.w;
            acc[3][0] += a.w * w.x; acc[3][1] += a.w * w.y; acc[3][2] += a.w * w.z; acc[3][3] += a.w * w.w;
        }
        __syncthreads();
    }

    float4 bv4 = *(const float4*)(bias + bn + (tc << 2));
#pragma unroll
    for (int i = 0; i < 4; i++) {
        float4 o;
        o.x = acc[i][0] + bv4.x;
        o.y = acc[i][1] + bv4.y;
        o.z = acc[i][2] + bv4.z;
        o.w = acc[i][3] + bv4.w;
        *(float4*)(C + (size_t)(bm + (tr << 2) + i) * N + bn + (tc << 2)) = o;
    }
}

// ---------------------------------------------------------------------------
// M=128 step-GEMM core, SCALAR FFMA, strided A/W (for split-K),
// register-prefetch pipelined. One block: C[0:128, 0:32] over Klen k-range.
// ---------------------------------------------------------------------------
__device__ __forceinline__
void gemm_m128_core(float As[16][128], float Bs[16][32],
                    const float* __restrict__ A, int lda,
                    const float* __restrict__ Wn, int ldw,
                    const float* __restrict__ biasn, float* __restrict__ Cn,
                    int ldc, int Klen)
{
    const int tid = threadIdx.x;
    const int lm  = tid & 127;            // A-load row
    const int lkh = (tid >> 7) << 3;      // A-load k base: 0 or 8
    const int bn  = tid >> 2;             // W-load row (tid<128 -> 0..31)
    const int bk  = (tid & 3) << 2;       // W-load k base
    const int ty  = tid >> 3;             // 0..31
    const int tx  = tid & 7;              // 0..7

    const float* Ap = A + (size_t)lm * lda + lkh;
    const float* Wp = Wn + (size_t)bn * ldw + bk;

    float acc[4][4];
#pragma unroll
    for (int i = 0; i < 4; i++)
#pragma unroll
        for (int j = 0; j < 4; j++) acc[i][j] = 0.0f;

    float4 a0 = *(const float4*)(Ap);
    float4 a1 = *(const float4*)(Ap + 4);
    float4 w  = make_float4(0.f, 0.f, 0.f, 0.f);
    if (tid < 128) w = *(const float4*)(Wp);

    for (int k0 = 0; k0 < Klen; k0 += 16) {
        As[lkh + 0][lm] = a0.x; As[lkh + 1][lm] = a0.y;
        As[lkh + 2][lm] = a0.z; As[lkh + 3][lm] = a0.w;
        As[lkh + 4][lm] = a1.x; As[lkh + 5][lm] = a1.y;
        As[lkh + 6][lm] = a1.z; As[lkh + 7][lm] = a1.w;
        if (tid < 128) {
            Bs[bk + 0][bn] = w.x; Bs[bk + 1][bn] = w.y;
            Bs[bk + 2][bn] = w.z; Bs[bk + 3][bn] = w.w;
        }
        __syncthreads();
        if (k0 + 16 < Klen) {
            a0 = *(const float4*)(Ap + k0 + 16);
            a1 = *(const float4*)(Ap + k0 + 20);
            if (tid < 128) w = *(const float4*)(Wp + k0 + 16);
        }
#pragma unroll
        for (int kk = 0; kk < 16; kk++) {
            float4 a = *(const float4*)&As[kk][ty << 2];
            float4 b = *(const float4*)&Bs[kk][tx << 2];
            acc[0][0] += a.x * b.x; acc[0][1] += a.x * b.y; acc[0][2] += a.x * b.z; acc[0][3] += a.x * b.w;
            acc[1][0] += a.y * b.x; acc[1][1] += a.y * b.y; acc[1][2] += a.y * b.z; acc[1][3] += a.y * b.w;
            acc[2][0] += a.z * b.x; acc[2][1] += a.z * b.y; acc[2][2] += a.z * b.z; acc[2][3] += a.z * b.w;
            acc[3][0] += a.w * b.x; acc[3][1] += a.w * b.y; acc[3][2] += a.w * b.z; acc[3][3] += a.w * b.w;
        }
        __syncthreads();
    }

    float4 bv = *(const float4*)(biasn + (tx << 2));
#pragma unroll
    for (int i = 0; i < 4; i++) {
        float4 o;
        o.x = acc[i][0] + bv.x;
        o.y = acc[i][1] + bv.y;
        o.z = acc[i][2] + bv.z;
        o.w = acc[i][3] + bv.w;
        *(float4*)(Cn + (size_t)((ty << 2) + i) * ldc + (tx << 2)) = o;
    }
}

// step1: [ps | he] = h @ [Ws ; Wh]^T + bias, split-K x2.  grid = 352 blocks.
__global__ __launch_bounds__(256, 2)
void step1_kernel(const float* __restrict__ Ws, const float* __restrict__ bs,
                  const float* __restrict__ Wh, const float* __restrict__ bh)
{
    __shared__ float As[16][128];
    __shared__ float Bs[16][32];
    const int KH = H_ / 2;                        // 512
    int id = blockIdx.x;
    int half = (id >= 176) ? 1 : 0;
    int n0 = (id - half * 176) << 5;
    const float* Ab = g_h + half * KH;
    if (n0 < 5 * H_) {
        gemm_m128_core(As, Bs, Ab, H_,
                       Ws + (size_t)n0 * H_ + half * KH, H_,
                       half ? g_zero : (bs + n0),
                       (half ? g_ps2 : g_ps) + n0, 5 * H_, KH);
    } else {
        int m = n0 - 5 * H_;
        gemm_m128_core(As, Bs, Ab, H_,
                       Wh + (size_t)m * H_ + half * KH, H_,
                       half ? g_zero : (bh + m),
                       (half ? g_he2 : g_he) + m, A_, KH);
    }
}

// step2: pa = ctx @ Wa^T + ba, split-K x2.  grid = 320 blocks.
__global__ __launch_bounds__(256, 2)
void step2_kernel(const float* __restrict__ Wa, const float* __restrict__ ba)
{
    __shared__ float As[16][128];
    __shared__ float Bs[16][32];
    const int KH = V_ / 2;                        // 1024
    int id = blockIdx.x;
    int half = (id >= 160) ? 1 : 0;
    int n0 = (id - half * 160) << 5;
    gemm_m128_core(As, Bs, g_ctx + half * KH, V_,
                   Wa + (size_t)n0 * V_ + half * KH, V_,
                   half ? g_zero : (ba + n0),
                   (half ? g_pa2 : g_pa) + n0, 5 * H_, KH);
}

// ---------------------------------------------------------------------------
// Attention: logits -> masked softmax -> ctx. One block per batch element.
// ---------------------------------------------------------------------------
__global__ __launch_bounds__(256)
void attn_kernel(const float* __restrict__ visual,
                 const float* __restrict__ Wp, const float* __restrict__ bp,
                 const int* __restrict__ ls_rois)
{
    int b = blockIdx.x;
    int tid = threadIdx.x;
    int warp = tid >> 5, lane = tid & 31;

    __shared__ float he_s[A_];
    __shared__ float wp_s[A_];
    __shared__ float att[NROI];

    if (tid < 128) {
        float4 h0 = ((const float4*)(g_he + b * A_))[tid];
        float4 h1 = ((const float4*)(g_he2 + b * A_))[tid];
        ((float4*)he_s)[tid] = make_float4(h0.x + h1.x, h0.y + h1.y,
                                           h0.z + h1.z, h0.w + h1.w);
        ((float4*)wp_s)[tid] = ((const float4*)Wp)[tid];
    }
    __syncthreads();

    int L = ls_rois[b];

    for (int n = warp; n < NROI; n += 8) {
        float s = 0.0f;
        if (n < L) {
            const float4* vrow = (const float4*)(g_va + ((size_t)b * NROI + n) * A_);
            const float4* he4 = (const float4*)he_s;
            const float4* wp4 = (const float4*)wp_s;
#pragma unroll
            for (int a4 = lane; a4 < A_ / 4; a4 += 32) {
                float4 v = vrow[a4];
                float4 h = he4[a4];
                float4 p = wp4[a4];
                s += p.x * fmaxf(v.x + h.x, 0.0f);
                s += p.y * fmaxf(v.y + h.y, 0.0f);
                s += p.z * fmaxf(v.z + h.z, 0.0f);
                s += p.w * fmaxf(v.w + h.w, 0.0f);
            }
        }
#pragma unroll
        for (int o = 16; o; o >>= 1) s += __shfl_xor_sync(0xffffffffu, s, o);
        if (lane == 0) att[n] = s + bp[0];
    }
    __syncthreads();

    if (tid == 0) {
        float mx = -3.0e38f;
        for (int n = 0; n < L; n++) mx = fmaxf(mx, att[n]);
        float den = 0.0f;
        for (int n = 0; n < L; n++) { float e = expf(att[n] - mx); att[n] = e; den += e; }
        float inv = 1.0f / den;
        for (int n = 0; n < L; n++) att[n] *= inv;
        for (int n = L; n < NROI; n++) att[n] = 0.0f;
    }
    __syncthreads();

    const float4* vb4 = (const float4*)(visual + (size_t)b * NROI * V_);
    float4* ctx4 = (float4*)(g_ctx + b * V_);
#pragma unroll
    for (int v4 = tid; v4 < V_ / 4; v4 += 256) {
        float4 s = make_float4(0.f, 0.f, 0.f, 0.f);
#pragma unroll 8
        for (int n = 0; n < NROI; n++) {
            float a = att[n];
            float4 x = vb4[(size_t)n * (V_ / 4) + v4];
            s.x += a * x.x; s.y += a * x.y; s.z += a * x.z; s.w += a * x.w;
        }
        ctx4[v4] = s;
    }
}

// ---------------------------------------------------------------------------
// LSTM gates + highway + state update + output projection for step t.
// Sums split-K halves of ps/pa.
// ---------------------------------------------------------------------------
__global__ __launch_bounds__(256)
void gate_kernel(const float* __restrict__ Wo, const float* __restrict__ bo,
                 const int* __restrict__ seq_lens, float* __restrict__ y, int t)
{
    const int HQ = H_ / 4;   // 256
    int b = blockIdx.x;
    int tid = threadIdx.x;
    bool valid = (t < seq_lens[b]);

    const float4* pi = (const float4*)(g_pi + ((size_t)b * T_ + t) * (6 * H_));
    const float4* ps = (const float4*)(g_ps + (size_t)b * (5 * H_));
    const float4* ps2 = (const float4*)(g_ps2 + (size_t)b * (5 * H_));
    const float4* pa = (const float4*)(g_pa + (size_t)b * (5 * H_));
    const float4* pa2 = (const float4*)(g_pa2 + (size_t)b * (5 * H_));
    float4* h4 = (float4*)(g_h + b * H_);
    float4* c4 = (float4*)(g_c + b * H_);

    float g[5][4];
#pragma unroll
    for (int kgate = 0; kgate < 5; kgate++) {
        float4 a = pi[kgate * HQ + tid];
        float4 q0 = ps[kgate * HQ + tid];
        float4 q1 = ps2[kgate * HQ + tid];
        float4 r0 = pa[kgate * HQ + tid];
        float4 r1 = pa2[kgate * HQ + tid];
        g[kgate][0] = a.x + q0.x + q1.x + r0.x + r1.x;
        g[kgate][1] = a.y + q0.y + q1.y + r0.y + r1.y;
        g[kgate][2] = a.z + q0.z + q1.z + r0.z + r1.z;
        g[kgate][3] = a.w + q0.w + q1.w + r0.w + r1.w;
    }
    float4 s5 = pi[5 * HQ + tid];
    float pi5[4] = {s5.x, s5.y, s5.z, s5.w};
    float4 cv = c4[tid];
    float cc[4] = {cv.x, cv.y, cv.z, cv.w};
    float4 wo = ((const float4*)Wo)[tid];
    float wof[4] = {wo.x, wo.y, wo.z, wo.w};

    float out[4], mem[4], part = 0.0f;
#pragma unroll
    for (int e = 0; e < 4; e++) {
        float ig = sigmoidf(g[0][e]);
        float fg = sigmoidf(g[1][e]);
        float mi = tanhf(g[2][e]);
        float og = sigmoidf(g[3][e]);
        float m  = ig * mi + fg * cc[e];
        float o  = og * tanhf(m);
        float hw = sigmoidf(g[4][e]);
        out[e] = hw * o + (1.0f - hw) * pi5[e];
        mem[e] = m;
        part += out[e] * wof[e];
    }

    if (valid) {
        h4[tid] = make_float4(out[0], out[1], out[2], out[3]);
        c4[tid] = make_float4(mem[0], mem[1], mem[2], mem[3]);
    }

#pragma unroll
    for (int o = 16; o; o >>= 1) part += __shfl_xor_sync(0xffffffffu, part, o);
    __shared__ float red[8];
    if ((tid & 31) == 0) red[tid >> 5] = part;
    __syncthreads();
    if (tid == 0) {
        float s = 0.0f;
#pragma unroll
        for (int w = 0; w < 8; w++) s += red[w];
        y[b * T_ + t] = valid ? (s + bo[0]) : 0.0f;
    }
}

// ---------------------------------------------------------------------------
extern "C" void kernel_launch(void* const* d_in, const int* in_sizes, int n_in,
                              void* d_out, int out_size)
{
    const float* x      = (const float*)d_in[0];
    const float* visual = (const float*)d_in[1];
    const float* Wi     = (const float*)d_in[2];
    const float* bi     = (const float*)d_in[3];
    const float* Ws     = (const float*)d_in[4];
    const float* bs     = (const float*)d_in[5];
    const float* Wa     = (const float*)d_in[6];
    const float* ba     = (const float*)d_in[7];
    const float* Wv     = (const float*)d_in[8];
    const float* bv     = (const float*)d_in[9];
    const float* Wh     = (const float*)d_in[10];
    const float* bh     = (const float*)d_in[11];
    const float* Wp     = (const float*)d_in[12];
    const float* bp     = (const float*)d_in[13];
    const float* W0h    = (const float*)d_in[14];
    const float* b0h    = (const float*)d_in[15];
    const float* W0c    = (const float*)d_in[16];
    const float* b0c    = (const float*)d_in[17];
    const float* Wo     = (const float*)d_in[18];
    const float* bo     = (const float*)d_in[19];
    const int* ls_rois  = (const int*)d_in[20];
    const int* seq_lens = (const int*)d_in[21];
    float* y = (float*)d_out;

    float *p_mean, *p_h, *p_c, *p_va, *p_pi;
    cudaGetSymbolAddress((void**)&p_mean, g_mean);
    cudaGetSymbolAddress((void**)&p_h,    g_h);
    cudaGetSymbolAddress((void**)&p_c,    g_c);
    cudaGetSymbolAddress((void**)&p_va,   g_va);
    cudaGetSymbolAddress((void**)&p_pi,   g_pi);

    // ---- loop-invariant precompute ----
    mean_vis_kernel<<<B_, 256>>>(visual, ls_rois);
    gemm_nt_bias<<<dim3(H_ / 64, B_ / 64), 256>>>(p_mean, W0h, b0h, p_h, B_, H_, V_);
    gemm_nt_bias<<<dim3(H_ / 64, B_ / 64), 256>>>(p_mean, W0c, b0c, p_c, B_, H_, V_);
    gemm_nt_bias<<<dim3(A_ / 64, (B_ * NROI) / 64), 256>>>(visual, Wv, bv, p_va,
                                                           B_ * NROI, A_, V_);
    gemm_nt_bias<<<dim3((6 * H_) / 64, (B_ * T_) / 64), 256>>>(x, Wi, bi, p_pi,
                                                               B_ * T_, 6 * H_, DIN);

    // ---- recurrent steps: 4 launches/step ----
    for (int t = 0; t < T_; t++) {
        step1_kernel<<<352, 256>>>(Ws, bs, Wh, bh);     // ps + he (split-K x2, scalar)
        attn_kernel<<<B_, 256>>>(visual, Wp, bp, ls_rois);
        step2_kernel<<<320, 256>>>(Wa, ba);             // pa (split-K x2, scalar)
        gate_kernel<<<B_, 256>>>(Wo, bo, seq_lens, y, t);
    }
}

// round 6
// speedup vs baseline: 2.0732x; 1.0398x over previous
#include <cuda_runtime.h>
#include <math.h>

// Problem dimensions (fixed)
#define B_   128
#define T_   32
#define DIN  1024
#define H_   1024
#define V_   2048
#define A_   512
#define NROI 64

#define NB   296          // persistent grid: exactly 2 blocks per SM (148 SMs)
#define SK   4            // split-K factor for step GEMMs

// ---------------- scratch (static device globals; no allocations) ----------
__device__ float g_mean[B_ * V_];                 // mean visual
__device__ float g_h[B_ * H_];                    // hidden state
__device__ float g_c[B_ * H_];                    // cell state
__device__ float g_va[(size_t)B_ * NROI * A_];    // visual attn enc
__device__ float g_pi[(size_t)B_ * T_ * 6 * H_];  // x projections (~100MB)
__device__ float g_ctx[B_ * V_];                  // context
__device__ float g_ps4[SK][B_ * 5 * H_];          // state proj, SK k-parts
__device__ float g_pa4[SK][B_ * 5 * H_];          // attn proj,  SK k-parts
__device__ float g_he4[SK][B_ * A_];              // h attn enc, SK k-parts
__device__ float g_zero[64];                      // zero bias (bss)

// grid-wide barrier state
__device__ unsigned int g_bar_arrive;
__device__ volatile unsigned int g_bar_gen;

__device__ __forceinline__ float sigmoidf(float x) { return 1.0f / (1.0f + expf(-x)); }

// ---------------------------------------------------------------------------
// Grid-wide barrier (all NB blocks co-resident by construction).
// Release: __threadfence before arrive; Acquire: __threadfence after spin
// (gpu-scope fence emits CCTL.IVALL -> L1 invalidate, so cross-SM data is fresh).
// ---------------------------------------------------------------------------
__device__ __forceinline__ void grid_sync()
{
    __syncthreads();
    if (threadIdx.x == 0) {
        unsigned int gen = g_bar_gen;
        __threadfence();
        if (atomicAdd(&g_bar_arrive, 1u) == NB - 1) {
            g_bar_arrive = 0;
            __threadfence();
            g_bar_gen = gen + 1;
        } else {
            while (g_bar_gen == gen) __nanosleep(64);
            __threadfence();
        }
    }
    __syncthreads();
}

// ---------------------------------------------------------------------------
// mean_vis[b,v] = sum_{n<L} visual[b,n,v] / L
// ---------------------------------------------------------------------------
__global__ void mean_vis_kernel(const float* __restrict__ visual,
                                const int* __restrict__ ls_rois)
{
    int b = blockIdx.x;
    int L = ls_rois[b];
    const float4* vb = (const float4*)(visual + (size_t)b * NROI * V_);
    float invL = 1.0f / (float)L;
    float4* out = (float4*)(g_mean + b * V_);
    for (int v4 = threadIdx.x; v4 < V_ / 4; v4 += blockDim.x) {
        float4 s = make_float4(0.f, 0.f, 0.f, 0.f);
#pragma unroll 4
        for (int n = 0; n < NROI; n++) {
            if (n < L) {
                float4 x = vb[(size_t)n * (V_ / 4) + v4];
                s.x += x.x; s.y += x.y; s.z += x.z; s.w += x.w;
            }
        }
        s.x *= invL; s.y *= invL; s.z *= invL; s.w *= invL;
        out[v4] = s;
    }
}

// ---------------------------------------------------------------------------
// Generic NT GEMM with bias (precompute path), register-prefetch pipelined,
// scalar FFMA (~88% of fp32 scalar peak). BM=BN=64, BK=16, 4x4/thread.
// ---------------------------------------------------------------------------
__global__ __launch_bounds__(256)
void gemm_nt_bias(const float* __restrict__ A, const float* __restrict__ W,
                  const float* __restrict__ bias, float* __restrict__ C,
                  int M, int N, int K)
{
    __shared__ float As[16][64];
    __shared__ float Bs[16][64];

    const int bm = blockIdx.y * 64;
    const int bn = blockIdx.x * 64;
    const int tid = threadIdx.x;
    const int tr = tid >> 4;
    const int tc = tid & 15;
    const int lr = tid >> 2;
    const int lc = (tid & 3) << 2;

    const float* Ap = A + (size_t)(bm + lr) * K + lc;
    const float* Wp = W + (size_t)(bn + lr) * K + lc;

    float acc[4][4];
#pragma unroll
    for (int i = 0; i < 4; i++)
#pragma unroll
        for (int j = 0; j < 4; j++) acc[i][j] = 0.0f;

    float4 av = *(const float4*)(Ap);
    float4 wv = *(const float4*)(Wp);

    for (int k0 = 0; k0 < K; k0 += 16) {
        As[lc + 0][lr] = av.x; As[lc + 1][lr] = av.y;
        As[lc + 2][lr] = av.z; As[lc + 3][lr] = av.w;
        Bs[lc + 0][lr] = wv.x; Bs[lc + 1][lr] = wv.y;
        Bs[lc + 2][lr] = wv.z; Bs[lc + 3][lr] = wv.w;
        __syncthreads();
        if (k0 + 16 < K) {
            av = *(const float4*)(Ap + k0 + 16);
            wv = *(const float4*)(Wp + k0 + 16);
        }
#pragma unroll
        for (int kk = 0; kk < 16; kk++) {
            float4 a = *(const float4*)&As[kk][tr << 2];
            float4 w = *(const float4*)&Bs[kk][tc << 2];
            acc[0][0] += a.x * w.x; acc[0][1] += a.x * w.y; acc[0][2] += a.x * w.z; acc[0][3] += a.x * w.w;
            acc[1][0] += a.y * w.x; acc[1][1] += a.y * w.y; acc[1][2] += a.y * w.z; acc[1][3] += a.y * w.w;
            acc[2][0] += a.z * w.x; acc[2][1] += a.z * w.y; acc[2][2] += a.z * w.z; acc[2][3] += a.z * w.w;
            acc[3][0] += a.w * w.x; acc[3][1] += a.w * w.y; acc[3][2] += a.w * w.z; acc[3][3] += a.w * w.w;
        }
        __syncthreads();
    }

    float4 bv4 = *(const float4*)(bias + bn + (tc << 2));
#pragma unroll
    for (int i = 0; i < 4; i++) {
        float4 o;
        o.x = acc[i][0] + bv4.x;
        o.y = acc[i][1] + bv4.y;
        o.z = acc[i][2] + bv4.z;
        o.w = acc[i][3] + bv4.w;
        *(float4*)(C + (size_t)(bm + (tr << 2) + i) * N + bn + (tc << 2)) = o;
    }
}

// ---------------------------------------------------------------------------
// M=128 step-GEMM tile core, scalar FFMA, strided A/W, register-prefetch.
// One call computes C[0:128, 0:32] over a Klen k-range.
// ---------------------------------------------------------------------------
__device__ __forceinline__
void gemm_m128_core(float As[16][128], float Bs[16][32],
                    const float* __restrict__ A, int lda,
                    const float* __restrict__ Wn, int ldw,
                    const float* __restrict__ biasn, float* __restrict__ Cn,
                    int ldc, int Klen)
{
    const int tid = threadIdx.x;
    const int lm  = tid & 127;
    const int lkh = (tid >> 7) << 3;
    const int bn  = tid >> 2;
    const int bk  = (tid & 3) << 2;
    const int ty  = tid >> 3;
    const int tx  = tid & 7;

    const float* Ap = A + (size_t)lm * lda + lkh;
    const float* Wp = Wn + (size_t)bn * ldw + bk;

    float acc[4][4];
#pragma unroll
    for (int i = 0; i < 4; i++)
#pragma unroll
        for (int j = 0; j < 4; j++) acc[i][j] = 0.0f;

    float4 a0 = *(const float4*)(Ap);
    float4 a1 = *(const float4*)(Ap + 4);
    float4 w  = make_float4(0.f, 0.f, 0.f, 0.f);
    if (tid < 128) w = *(const float4*)(Wp);

    for (int k0 = 0; k0 < Klen; k0 += 16) {
        As[lkh + 0][lm] = a0.x; As[lkh + 1][lm] = a0.y;
        As[lkh + 2][lm] = a0.z; As[lkh + 3][lm] = a0.w;
        As[lkh + 4][lm] = a1.x; As[lkh + 5][lm] = a1.y;
        As[lkh + 6][lm] = a1.z; As[lkh + 7][lm] = a1.w;
        if (tid < 128) {
            Bs[bk + 0][bn] = w.x; Bs[bk + 1][bn] = w.y;
            Bs[bk + 2][bn] = w.z; Bs[bk + 3][bn] = w.w;
        }
        __syncthreads();
        if (k0 + 16 < Klen) {
            a0 = *(const float4*)(Ap + k0 + 16);
            a1 = *(const float4*)(Ap + k0 + 20);
            if (tid < 128) w = *(const float4*)(Wp + k0 + 16);
        }
#pragma unroll
        for (int kk = 0; kk < 16; kk++) {
            float4 a = *(const float4*)&As[kk][ty << 2];
            float4 b = *(const float4*)&Bs[kk][tx << 2];
            acc[0][0] += a.x * b.x; acc[0][1] += a.x * b.y; acc[0][2] += a.x * b.z; acc[0][3] += a.x * b.w;
            acc[1][0] += a.y * b.x; acc[1][1] += a.y * b.y; acc[1][2] += a.y * b.z; acc[1][3] += a.y * b.w;
            acc[2][0] += a.z * b.x; acc[2][1] += a.z * b.y; acc[2][2] += a.z * b.z; acc[2][3] += a.z * b.w;
            acc[3][0] += a.w * b.x; acc[3][1] += a.w * b.y; acc[3][2] += a.w * b.z; acc[3][3] += a.w * b.w;
        }
        __syncthreads();
    }

    float4 bv = *(const float4*)(biasn + (tx << 2));
#pragma unroll
    for (int i = 0; i < 4; i++) {
        float4 o;
        o.x = acc[i][0] + bv.x;
        o.y = acc[i][1] + bv.y;
        o.z = acc[i][2] + bv.z;
        o.w = acc[i][3] + bv.w;
        *(float4*)(Cn + (size_t)((ty << 2) + i) * ldc + (tx << 2)) = o;
    }
}

// ---------------------------------------------------------------------------
// Attention work for one batch element (256 threads).
// ---------------------------------------------------------------------------
__device__ __forceinline__
void attn_work(int b, const float* __restrict__ visual,
               const float* __restrict__ Wp, const float* __restrict__ bp,
               const int* __restrict__ ls_rois,
               float* he_s, float* wp_s, float* att)
{
    int tid = threadIdx.x;
    int warp = tid >> 5, lane = tid & 31;

    if (tid < 128) {
        float4 h0 = ((const float4*)(g_he4[0] + b * A_))[tid];
        float4 h1 = ((const float4*)(g_he4[1] + b * A_))[tid];
        float4 h2 = ((const float4*)(g_he4[2] + b * A_))[tid];
        float4 h3 = ((const float4*)(g_he4[3] + b * A_))[tid];
        ((float4*)he_s)[tid] = make_float4(h0.x + h1.x + h2.x + h3.x,
                                           h0.y + h1.y + h2.y + h3.y,
                                           h0.z + h1.z + h2.z + h3.z,
                                           h0.w + h1.w + h2.w + h3.w);
        ((float4*)wp_s)[tid] = ((const float4*)Wp)[tid];
    }
    __syncthreads();

    int L = ls_rois[b];

    for (int n = warp; n < NROI; n += 8) {
        float s = 0.0f;
        if (n < L) {
            const float4* vrow = (const float4*)(g_va + ((size_t)b * NROI + n) * A_);
            const float4* he4 = (const float4*)he_s;
            const float4* wp4 = (const float4*)wp_s;
#pragma unroll
            for (int a4 = lane; a4 < A_ / 4; a4 += 32) {
                float4 v = vrow[a4];
                float4 h = he4[a4];
                float4 p = wp4[a4];
                s += p.x * fmaxf(v.x + h.x, 0.0f);
                s += p.y * fmaxf(v.y + h.y, 0.0f);
                s += p.z * fmaxf(v.z + h.z, 0.0f);
                s += p.w * fmaxf(v.w + h.w, 0.0f);
            }
        }
#pragma unroll
        for (int o = 16; o; o >>= 1) s += __shfl_xor_sync(0xffffffffu, s, o);
        if (lane == 0) att[n] = s + bp[0];
    }
    __syncthreads();

    if (tid == 0) {
        float mx = -3.0e38f;
        for (int n = 0; n < L; n++) mx = fmaxf(mx, att[n]);
        float den = 0.0f;
        for (int n = 0; n < L; n++) { float e = expf(att[n] - mx); att[n] = e; den += e; }
        float inv = 1.0f / den;
        for (int n = 0; n < L; n++) att[n] *= inv;
        for (int n = L; n < NROI; n++) att[n] = 0.0f;
    }
    __syncthreads();

    const float4* vb4 = (const float4*)(visual + (size_t)b * NROI * V_);
    float4* ctx4 = (float4*)(g_ctx + b * V_);
#pragma unroll
    for (int v4 = tid; v4 < V_ / 4; v4 += 256) {
        float4 s = make_float4(0.f, 0.f, 0.f, 0.f);
#pragma unroll 8
        for (int n = 0; n < NROI; n++) {
            float a = att[n];
            float4 x = vb4[(size_t)n * (V_ / 4) + v4];
            s.x += a * x.x; s.y += a * x.y; s.z += a * x.z; s.w += a * x.w;
        }
        ctx4[v4] = s;
    }
    __syncthreads();
}

// ---------------------------------------------------------------------------
// LSTM gates + highway + state update + y for one batch element, step t.
// Sums SK split-K partials of ps/pa.
// ---------------------------------------------------------------------------
__device__ __forceinline__
void gate_work(int b, int t, const float* __restrict__ Wo,
               const float* __restrict__ bo, const int* __restrict__ seq_lens,
               float* __restrict__ y, float* red)
{
    const int HQ = H_ / 4;   // 256
    int tid = threadIdx.x;
    bool valid = (t < seq_lens[b]);

    const float4* pi = (const float4*)(g_pi + ((size_t)b * T_ + t) * (6 * H_));
    float4* h4 = (float4*)(g_h + b * H_);
    float4* c4 = (float4*)(g_c + b * H_);

    float g[5][4];
#pragma unroll
    for (int kg = 0; kg < 5; kg++) {
        float4 a = pi[kg * HQ + tid];
        g[kg][0] = a.x; g[kg][1] = a.y; g[kg][2] = a.z; g[kg][3] = a.w;
#pragma unroll
        for (int kp = 0; kp < SK; kp++) {
            float4 q = ((const float4*)(g_ps4[kp] + (size_t)b * (5 * H_)))[kg * HQ + tid];
            float4 r = ((const float4*)(g_pa4[kp] + (size_t)b * (5 * H_)))[kg * HQ + tid];
            g[kg][0] += q.x + r.x; g[kg][1] += q.y + r.y;
            g[kg][2] += q.z + r.z; g[kg][3] += q.w + r.w;
        }
    }
    float4 s5 = pi[5 * HQ + tid];
    float pi5[4] = {s5.x, s5.y, s5.z, s5.w};
    float4 cv = c4[tid];
    float cc[4] = {cv.x, cv.y, cv.z, cv.w};
    float4 wo = ((const float4*)Wo)[tid];
    float wof[4] = {wo.x, wo.y, wo.z, wo.w};

    float out[4], mem[4], part = 0.0f;
#pragma unroll
    for (int e = 0; e < 4; e++) {
        float ig = sigmoidf(g[0][e]);
        float fg = sigmoidf(g[1][e]);
        float mi = tanhf(g[2][e]);
        float og = sigmoidf(g[3][e]);
        float m  = ig * mi + fg * cc[e];
        float o  = og * tanhf(m);
        float hw = sigmoidf(g[4][e]);
        out[e] = hw * o + (1.0f - hw) * pi5[e];
        mem[e] = m;
        part += out[e] * wof[e];
    }

    if (valid) {
        h4[tid] = make_float4(out[0], out[1], out[2], out[3]);
        c4[tid] = make_float4(mem[0], mem[1], mem[2], mem[3]);
    }

#pragma unroll
    for (int o = 16; o; o >>= 1) part += __shfl_xor_sync(0xffffffffu, part, o);
    if ((tid & 31) == 0) red[tid >> 5] = part;
    __syncthreads();
    if (tid == 0) {
        float s = 0.0f;
#pragma unroll
        for (int w = 0; w < 8; w++) s += red[w];
        y[b * T_ + t] = valid ? (s + bo[0]) : 0.0f;
    }
    __syncthreads();
}

// ---------------------------------------------------------------------------
// Persistent recurrent-loop kernel: all 32 steps, 4 phases per step,
// grid-wide barriers between phases. NB=296 blocks (2/SM, co-resident).
// ---------------------------------------------------------------------------
__global__ __launch_bounds__(256, 2)
void loop_kernel(const float* __restrict__ Ws, const float* __restrict__ bs,
                 const float* __restrict__ Wh, const float* __restrict__ bh,
                 const float* __restrict__ Wa, const float* __restrict__ ba,
                 const float* __restrict__ Wp, const float* __restrict__ bp,
                 const float* __restrict__ Wo, const float* __restrict__ bo,
                 const float* __restrict__ visual,
                 const int* __restrict__ ls_rois,
                 const int* __restrict__ seq_lens,
                 float* __restrict__ y)
{
    __shared__ float As[16][128];
    __shared__ float Bs[16][32];
    __shared__ float he_s[A_];
    __shared__ float wp_s[A_];
    __shared__ float att[NROI];
    __shared__ float red[8];

    const int KH1 = H_ / SK;   // 256
    const int KH2 = V_ / SK;   // 512
    const int NT1 = ((5 * H_ + A_) / 32) * SK;   // 704
    const int NT2 = ((5 * H_) / 32) * SK;        // 640

    for (int t = 0; t < T_; t++) {
        // ---- phase 1: [ps | he] = h @ [Ws ; Wh]^T (split-K x4) ----
        for (int tile = blockIdx.x; tile < NT1; tile += NB) {
            int nt = tile >> 2, kp = tile & 3;
            int n0 = nt << 5;
            const float* Ab = g_h + kp * KH1;
            if (n0 < 5 * H_) {
                gemm_m128_core(As, Bs, Ab, H_,
                               Ws + (size_t)n0 * H_ + kp * KH1, H_,
                               kp ? g_zero : (bs + n0),
                               g_ps4[kp] + n0, 5 * H_, KH1);
            } else {
                int m = n0 - 5 * H_;
                gemm_m128_core(As, Bs, Ab, H_,
                               Wh + (size_t)m * H_ + kp * KH1, H_,
                               kp ? g_zero : (bh + m),
                               g_he4[kp] + m, A_, KH1);
            }
        }
        grid_sync();

        // ---- phase 2: attention -> ctx ----
        if (blockIdx.x < B_)
            attn_work(blockIdx.x, visual, Wp, bp, ls_rois, he_s, wp_s, att);
        grid_sync();

        // ---- phase 3: pa = ctx @ Wa^T (split-K x4) ----
        for (int tile = blockIdx.x; tile < NT2; tile += NB) {
            int nt = tile >> 2, kp = tile & 3;
            int n0 = nt << 5;
            gemm_m128_core(As, Bs, g_ctx + kp * KH2, V_,
                           Wa + (size_t)n0 * V_ + kp * KH2, V_,
                           kp ? g_zero : (ba + n0),
                           g_pa4[kp] + n0, 5 * H_, KH2);
        }
        grid_sync();

        // ---- phase 4: gates + state update + y ----
        if (blockIdx.x < B_)
            gate_work(blockIdx.x, t, Wo, bo, seq_lens, y, red);
        grid_sync();
    }
}

// ---------------------------------------------------------------------------
extern "C" void kernel_launch(void* const* d_in, const int* in_sizes, int n_in,
                              void* d_out, int out_size)
{
    const float* x      = (const float*)d_in[0];
    const float* visual = (const float*)d_in[1];
    const float* Wi     = (const float*)d_in[2];
    const float* bi     = (const float*)d_in[3];
    const float* Ws     = (const float*)d_in[4];
    const float* bs     = (const float*)d_in[5];
    const float* Wa     = (const float*)d_in[6];
    const float* ba     = (const float*)d_in[7];
    const float* Wv     = (const float*)d_in[8];
    const float* bv     = (const float*)d_in[9];
    const float* Wh     = (const float*)d_in[10];
    const float* bh     = (const float*)d_in[11];
    const float* Wp     = (const float*)d_in[12];
    const float* bp     = (const float*)d_in[13];
    const float* W0h    = (const float*)d_in[14];
    const float* b0h    = (const float*)d_in[15];
    const float* W0c    = (const float*)d_in[16];
    const float* b0c    = (const float*)d_in[17];
    const float* Wo     = (const float*)d_in[18];
    const float* bo     = (const float*)d_in[19];
    const int* ls_rois  = (const int*)d_in[20];
    const int* seq_lens = (const int*)d_in[21];
    float* y = (float*)d_out;

    float *p_mean, *p_h, *p_c, *p_va, *p_pi;
    cudaGetSymbolAddress((void**)&p_mean, g_mean);
    cudaGetSymbolAddress((void**)&p_h,    g_h);
    cudaGetSymbolAddress((void**)&p_c,    g_c);
    cudaGetSymbolAddress((void**)&p_va,   g_va);
    cudaGetSymbolAddress((void**)&p_pi,   g_pi);

    // ---- loop-invariant precompute ----
    mean_vis_kernel<<<B_, 256>>>(visual, ls_rois);
    gemm_nt_bias<<<dim3(H_ / 64, B_ / 64), 256>>>(p_mean, W0h, b0h, p_h, B_, H_, V_);
    gemm_nt_bias<<<dim3(H_ / 64, B_ / 64), 256>>>(p_mean, W0c, b0c, p_c, B_, H_, V_);
    gemm_nt_bias<<<dim3(A_ / 64, (B_ * NROI) / 64), 256>>>(visual, Wv, bv, p_va,
                                                           B_ * NROI, A_, V_);
    gemm_nt_bias<<<dim3((6 * H_) / 64, (B_ * T_) / 64), 256>>>(x, Wi, bi, p_pi,
                                                               B_ * T_, 6 * H_, DIN);

    // ---- entire recurrent loop: ONE persistent kernel ----
    loop_kernel<<<NB, 256>>>(Ws, bs, Wh, bh, Wa, ba, Wp, bp, Wo, bo,
                             visual, ls_rois, seq_lens, y);
}

// round 7
// speedup vs baseline: 2.2804x; 1.0999x over previous
#include <cuda_runtime.h>
#include <math.h>

// Problem dimensions (fixed)
#define B_   128
#define T_   32
#define DIN  1024
#define H_   1024
#define V_   2048
#define A_   512
#define NROI 64

#define NB   296          // persistent grid: exactly 2 blocks per SM (148 SMs)
#define SK1  8            // split-K for ps/he (K=1024 -> Klen 128)
#define SK2  16           // split-K for pa   (K=2048 -> Klen 128)

// ---------------- scratch (static device globals; no allocations) ----------
__device__ float g_mean[B_ * V_];                 // mean visual
__device__ float g_h[B_ * H_];                    // hidden state
__device__ float g_c[B_ * H_];                    // cell state
__device__ float g_va[(size_t)B_ * NROI * A_];    // visual attn enc
__device__ float g_pi[(size_t)B_ * T_ * 6 * H_];  // x projections (~100MB)
__device__ float g_ctx[B_ * V_];                  // context
__device__ float g_ps4[SK1][B_ * 5 * H_];         // state proj partials (21MB)
__device__ float g_he4[SK1][B_ * A_];             // h attn enc partials
__device__ float g_pa4[SK2][B_ * 5 * H_];         // attn proj partials (42MB)
__device__ float g_zero[64];                      // zero bias (bss)

// grid-wide barrier state
__device__ unsigned int g_bar_arrive;
__device__ volatile unsigned int g_bar_gen;

__device__ __forceinline__ float sigmoidf(float x) { return 1.0f / (1.0f + expf(-x)); }

// ---------------------------------------------------------------------------
// Grid-wide barrier (all NB blocks co-resident by construction).
// ---------------------------------------------------------------------------
__device__ __forceinline__ void grid_sync()
{
    __syncthreads();
    if (threadIdx.x == 0) {
        unsigned int gen = g_bar_gen;
        __threadfence();
        if (atomicAdd(&g_bar_arrive, 1u) == NB - 1) {
            g_bar_arrive = 0;
            __threadfence();
            g_bar_gen = gen + 1;
        } else {
            while (g_bar_gen == gen) __nanosleep(64);
            __threadfence();
        }
    }
    __syncthreads();
}

// ---------------------------------------------------------------------------
// mean_vis[b,v] = sum_{n<L} visual[b,n,v] / L
// ---------------------------------------------------------------------------
__global__ void mean_vis_kernel(const float* __restrict__ visual,
                                const int* __restrict__ ls_rois)
{
    int b = blockIdx.x;
    int L = ls_rois[b];
    const float4* vb = (const float4*)(visual + (size_t)b * NROI * V_);
    float invL = 1.0f / (float)L;
    float4* out = (float4*)(g_mean + b * V_);
    for (int v4 = threadIdx.x; v4 < V_ / 4; v4 += blockDim.x) {
        float4 s = make_float4(0.f, 0.f, 0.f, 0.f);
#pragma unroll 4
        for (int n = 0; n < NROI; n++) {
            if (n < L) {
                float4 x = vb[(size_t)n * (V_ / 4) + v4];
                s.x += x.x; s.y += x.y; s.z += x.z; s.w += x.w;
            }
        }
        s.x *= invL; s.y *= invL; s.z *= invL; s.w *= invL;
        out[v4] = s;
    }
}

// ---------------------------------------------------------------------------
// Generic NT GEMM with bias (precompute path), register-prefetch pipelined,
// scalar FFMA (~88% of fp32 scalar peak). BM=BN=64, BK=16, 4x4/thread.
// ---------------------------------------------------------------------------
__global__ __launch_bounds__(256)
void gemm_nt_bias(const float* __restrict__ A, const float* __restrict__ W,
                  const float* __restrict__ bias, float* __restrict__ C,
                  int M, int N, int K)
{
    __shared__ float As[16][64];
    __shared__ float Bs[16][64];

    const int bm = blockIdx.y * 64;
    const int bn = blockIdx.x * 64;
    const int tid = threadIdx.x;
    const int tr = tid >> 4;
    const int tc = tid & 15;
    const int lr = tid >> 2;
    const int lc = (tid & 3) << 2;

    const float* Ap = A + (size_t)(bm + lr) * K + lc;
    const float* Wp = W + (size_t)(bn + lr) * K + lc;

    float acc[4][4];
#pragma unroll
    for (int i = 0; i < 4; i++)
#pragma unroll
        for (int j = 0; j < 4; j++) acc[i][j] = 0.0f;

    float4 av = *(const float4*)(Ap);
    float4 wv = *(const float4*)(Wp);

    for (int k0 = 0; k0 < K; k0 += 16) {
        As[lc + 0][lr] = av.x; As[lc + 1][lr] = av.y;
        As[lc + 2][lr] = av.z; As[lc + 3][lr] = av.w;
        Bs[lc + 0][lr] = wv.x; Bs[lc + 1][lr] = wv.y;
        Bs[lc + 2][lr] = wv.z; Bs[lc + 3][lr] = wv.w;
        __syncthreads();
        if (k0 + 16 < K) {
            av = *(const float4*)(Ap + k0 + 16);
            wv = *(const float4*)(Wp + k0 + 16);
        }
#pragma unroll
        for (int kk = 0; kk < 16; kk++) {
            float4 a = *(const float4*)&As[kk][tr << 2];
            float4 w = *(const float4*)&Bs[kk][tc << 2];
            acc[0][0] += a.x * w.x; acc[0][1] += a.x * w.y; acc[0][2] += a.x * w.z; acc[0][3] += a.x * w.w;
            acc[1][0] += a.y * w.x; acc[1][1] += a.y * w.y; acc[1][2] += a.y * w.z; acc[1][3] += a.y * w.w;
            acc[2][0] += a.z * w.x; acc[2][1] += a.z * w.y; acc[2][2] += a.z * w.z; acc[2][3] += a.z * w.w;
            acc[3][0] += a.w * w.x; acc[3][1] += a.w * w.y; acc[3][2] += a.w * w.z; acc[3][3] += a.w * w.w;
        }
        __syncthreads();
    }

    float4 bv4 = *(const float4*)(bias + bn + (tc << 2));
#pragma unroll
    for (int i = 0; i < 4; i++) {
        float4 o;
        o.x = acc[i][0] + bv4.x;
        o.y = acc[i][1] + bv4.y;
        o.z = acc[i][2] + bv4.z;
        o.w = acc[i][3] + bv4.w;
        *(float4*)(C + (size_t)(bm + (tr << 2) + i) * N + bn + (tc << 2)) = o;
    }
}

// ---------------------------------------------------------------------------
// M=128 step-GEMM tile core, scalar FFMA, strided A/W, register-prefetch.
// One call computes C[0:128, 0:32] over a Klen k-range.
// ---------------------------------------------------------------------------
__device__ __forceinline__
void gemm_m128_core(float As[16][128], float Bs[16][32],
                    const float* __restrict__ A, int lda,
                    const float* __restrict__ Wn, int ldw,
                    const float* __restrict__ biasn, float* __restrict__ Cn,
                    int ldc, int Klen)
{
    const int tid = threadIdx.x;
    const int lm  = tid & 127;
    const int lkh = (tid >> 7) << 3;
    const int bn  = tid >> 2;
    const int bk  = (tid & 3) << 2;
    const int ty  = tid >> 3;
    const int tx  = tid & 7;

    const float* Ap = A + (size_t)lm * lda + lkh;
    const float* Wp = Wn + (size_t)bn * ldw + bk;

    float acc[4][4];
#pragma unroll
    for (int i = 0; i < 4; i++)
#pragma unroll
        for (int j = 0; j < 4; j++) acc[i][j] = 0.0f;

    float4 a0 = *(const float4*)(Ap);
    float4 a1 = *(const float4*)(Ap + 4);
    float4 w  = make_float4(0.f, 0.f, 0.f, 0.f);
    if (tid < 128) w = *(const float4*)(Wp);

    for (int k0 = 0; k0 < Klen; k0 += 16) {
        As[lkh + 0][lm] = a0.x; As[lkh + 1][lm] = a0.y;
        As[lkh + 2][lm] = a0.z; As[lkh + 3][lm] = a0.w;
        As[lkh + 4][lm] = a1.x; As[lkh + 5][lm] = a1.y;
        As[lkh + 6][lm] = a1.z; As[lkh + 7][lm] = a1.w;
        if (tid < 128) {
            Bs[bk + 0][bn] = w.x; Bs[bk + 1][bn] = w.y;
            Bs[bk + 2][bn] = w.z; Bs[bk + 3][bn] = w.w;
        }
        __syncthreads();
        if (k0 + 16 < Klen) {
            a0 = *(const float4*)(Ap + k0 + 16);
            a1 = *(const float4*)(Ap + k0 + 20);
            if (tid < 128) w = *(const float4*)(Wp + k0 + 16);
        }
#pragma unroll
        for (int kk = 0; kk < 16; kk++) {
            float4 a = *(const float4*)&As[kk][ty << 2];
            float4 b = *(const float4*)&Bs[kk][tx << 2];
            acc[0][0] += a.x * b.x; acc[0][1] += a.x * b.y; acc[0][2] += a.x * b.z; acc[0][3] += a.x * b.w;
            acc[1][0] += a.y * b.x; acc[1][1] += a.y * b.y; acc[1][2] += a.y * b.z; acc[1][3] += a.y * b.w;
            acc[2][0] += a.z * b.x; acc[2][1] += a.z * b.y; acc[2][2] += a.z * b.z; acc[2][3] += a.z * b.w;
            acc[3][0] += a.w * b.x; acc[3][1] += a.w * b.y; acc[3][2] += a.w * b.z; acc[3][3] += a.w * b.w;
        }
        __syncthreads();
    }

    float4 bv = *(const float4*)(biasn + (tx << 2));
#pragma unroll
    for (int i = 0; i < 4; i++) {
        float4 o;
        o.x = acc[i][0] + bv.x;
        o.y = acc[i][1] + bv.y;
        o.z = acc[i][2] + bv.z;
        o.w = acc[i][3] + bv.w;
        *(float4*)(Cn + (size_t)((ty << 2) + i) * ldc + (tx << 2)) = o;
    }
}

// ---------------------------------------------------------------------------
// Attention work for one batch element (256 threads). Sums SK1 he partials.
// ---------------------------------------------------------------------------
__device__ __forceinline__
void attn_work(int b, const float* __restrict__ visual,
               const float* __restrict__ Wp, const float* __restrict__ bp,
               const int* __restrict__ ls_rois,
               float* he_s, float* wp_s, float* att)
{
    int tid = threadIdx.x;
    int warp = tid >> 5, lane = tid & 31;

    if (tid < 128) {
        float4 hsum = make_float4(0.f, 0.f, 0.f, 0.f);
#pragma unroll
        for (int kp = 0; kp < SK1; kp++) {
            float4 hv = ((const float4*)(g_he4[kp] + b * A_))[tid];
            hsum.x += hv.x; hsum.y += hv.y; hsum.z += hv.z; hsum.w += hv.w;
        }
        ((float4*)he_s)[tid] = hsum;
        ((float4*)wp_s)[tid] = ((const float4*)Wp)[tid];
    }
    __syncthreads();

    int L = ls_rois[b];

    for (int n = warp; n < NROI; n += 8) {
        float s = 0.0f;
        if (n < L) {
            const float4* vrow = (const float4*)(g_va + ((size_t)b * NROI + n) * A_);
            const float4* he4 = (const float4*)he_s;
            const float4* wp4 = (const float4*)wp_s;
#pragma unroll
            for (int a4 = lane; a4 < A_ / 4; a4 += 32) {
                float4 v = vrow[a4];
                float4 h = he4[a4];
                float4 p = wp4[a4];
                s += p.x * fmaxf(v.x + h.x, 0.0f);
                s += p.y * fmaxf(v.y + h.y, 0.0f);
                s += p.z * fmaxf(v.z + h.z, 0.0f);
                s += p.w * fmaxf(v.w + h.w, 0.0f);
            }
        }
#pragma unroll
        for (int o = 16; o; o >>= 1) s += __shfl_xor_sync(0xffffffffu, s, o);
        if (lane == 0) att[n] = s + bp[0];
    }
    __syncthreads();

    if (tid == 0) {
        float mx = -3.0e38f;
        for (int n = 0; n < L; n++) mx = fmaxf(mx, att[n]);
        float den = 0.0f;
        for (int n = 0; n < L; n++) { float e = expf(att[n] - mx); att[n] = e; den += e; }
        float inv = 1.0f / den;
        for (int n = 0; n < L; n++) att[n] *= inv;
        for (int n = L; n < NROI; n++) att[n] = 0.0f;
    }
    __syncthreads();

    const float4* vb4 = (const float4*)(visual + (size_t)b * NROI * V_);
    float4* ctx4 = (float4*)(g_ctx + b * V_);
#pragma unroll
    for (int v4 = tid; v4 < V_ / 4; v4 += 256) {
        float4 s = make_float4(0.f, 0.f, 0.f, 0.f);
#pragma unroll 8
        for (int n = 0; n < NROI; n++) {
            float a = att[n];
            float4 x = vb4[(size_t)n * (V_ / 4) + v4];
            s.x += a * x.x; s.y += a * x.y; s.z += a * x.z; s.w += a * x.w;
        }
        ctx4[v4] = s;
    }
    __syncthreads();
}

// ---------------------------------------------------------------------------
// LSTM gates + highway + state update + y for one batch element, step t.
// Sums SK1 ps partials + SK2 pa partials.
// ---------------------------------------------------------------------------
__device__ __forceinline__
void gate_work(int b, int t, const float* __restrict__ Wo,
               const float* __restrict__ bo, const int* __restrict__ seq_lens,
               float* __restrict__ y, float* red)
{
    const int HQ = H_ / 4;   // 256
    int tid = threadIdx.x;
    bool valid = (t < seq_lens[b]);

    const float4* pi = (const float4*)(g_pi + ((size_t)b * T_ + t) * (6 * H_));
    float4* h4 = (float4*)(g_h + b * H_);
    float4* c4 = (float4*)(g_c + b * H_);

    float g[5][4];
#pragma unroll
    for (int kg = 0; kg < 5; kg++) {
        float4 a = pi[kg * HQ + tid];
        float gx = a.x, gy = a.y, gz = a.z, gw = a.w;
#pragma unroll
        for (int kp = 0; kp < SK1; kp++) {
            float4 q = ((const float4*)(g_ps4[kp] + (size_t)b * (5 * H_)))[kg * HQ + tid];
            gx += q.x; gy += q.y; gz += q.z; gw += q.w;
        }
#pragma unroll
        for (int kp = 0; kp < SK2; kp++) {
            float4 r = ((const float4*)(g_pa4[kp] + (size_t)b * (5 * H_)))[kg * HQ + tid];
            gx += r.x; gy += r.y; gz += r.z; gw += r.w;
        }
        g[kg][0] = gx; g[kg][1] = gy; g[kg][2] = gz; g[kg][3] = gw;
    }
    float4 s5 = pi[5 * HQ + tid];
    float pi5[4] = {s5.x, s5.y, s5.z, s5.w};
    float4 cv = c4[tid];
    float cc[4] = {cv.x, cv.y, cv.z, cv.w};
    float4 wo = ((const float4*)Wo)[tid];
    float wof[4] = {wo.x, wo.y, wo.z, wo.w};

    float out[4], mem[4], part = 0.0f;
#pragma unroll
    for (int e = 0; e < 4; e++) {
        float ig = sigmoidf(g[0][e]);
        float fg = sigmoidf(g[1][e]);
        float mi = tanhf(g[2][e]);
        float og = sigmoidf(g[3][e]);
        float m  = ig * mi + fg * cc[e];
        float o  = og * tanhf(m);
        float hw = sigmoidf(g[4][e]);
        out[e] = hw * o + (1.0f - hw) * pi5[e];
        mem[e] = m;
        part += out[e] * wof[e];
    }

    if (valid) {
        h4[tid] = make_float4(out[0], out[1], out[2], out[3]);
        c4[tid] = make_float4(mem[0], mem[1], mem[2], mem[3]);
    }

#pragma unroll
    for (int o = 16; o; o >>= 1) part += __shfl_xor_sync(0xffffffffu, part, o);
    if ((tid & 31) == 0) red[tid >> 5] = part;
    __syncthreads();
    if (tid == 0) {
        float s = 0.0f;
#pragma unroll
        for (int w = 0; w < 8; w++) s += red[w];
        y[b * T_ + t] = valid ? (s + bo[0]) : 0.0f;
    }
    __syncthreads();
}

// ---------------------------------------------------------------------------
// Persistent recurrent-loop kernel: all 32 steps, 4 phases per step.
// Uniform Klen=128 GEMM tiles to minimize phase makespan quantization.
// ---------------------------------------------------------------------------
__global__ __launch_bounds__(256, 2)
void loop_kernel(const float* __restrict__ Ws, const float* __restrict__ bs,
                 const float* __restrict__ Wh, const float* __restrict__ bh,
                 const float* __restrict__ Wa, const float* __restrict__ ba,
                 const float* __restrict__ Wp, const float* __restrict__ bp,
                 const float* __restrict__ Wo, const float* __restrict__ bo,
                 const float* __restrict__ visual,
                 const int* __restrict__ ls_rois,
                 const int* __restrict__ seq_lens,
                 float* __restrict__ y)
{
    __shared__ float As[16][128];
    __shared__ float Bs[16][32];
    __shared__ float he_s[A_];
    __shared__ float wp_s[A_];
    __shared__ float att[NROI];
    __shared__ float red[8];

    const int KL = 128;                          // uniform Klen
    const int NT1 = ((5 * H_ + A_) / 32) * SK1;  // 176*8 = 1408
    const int NT2 = ((5 * H_) / 32) * SK2;       // 160*16 = 2560

    for (int t = 0; t < T_; t++) {
        // ---- phase 1: [ps | he] = h @ [Ws ; Wh]^T (split-K x8) ----
        for (int tile = blockIdx.x; tile < NT1; tile += NB) {
            int nt = tile >> 3, kp = tile & 7;
            int n0 = nt << 5;
            const float* Ab = g_h + kp * KL;
            if (n0 < 5 * H_) {
                gemm_m128_core(As, Bs, Ab, H_,
                               Ws + (size_t)n0 * H_ + kp * KL, H_,
                               kp ? g_zero : (bs + n0),
                               g_ps4[kp] + n0, 5 * H_, KL);
            } else {
                int m = n0 - 5 * H_;
                gemm_m128_core(As, Bs, Ab, H_,
                               Wh + (size_t)m * H_ + kp * KL, H_,
                               kp ? g_zero : (bh + m),
                               g_he4[kp] + m, A_, KL);
            }
        }
        grid_sync();

        // ---- phase 2: attention -> ctx ----
        if (blockIdx.x < B_)
            attn_work(blockIdx.x, visual, Wp, bp, ls_rois, he_s, wp_s, att);
        grid_sync();

        // ---- phase 3: pa = ctx @ Wa^T (split-K x16) ----
        for (int tile = blockIdx.x; tile < NT2; tile += NB) {
            int nt = tile >> 4, kp = tile & 15;
            int n0 = nt << 5;
            gemm_m128_core(As, Bs, g_ctx + kp * KL, V_,
                           Wa + (size_t)n0 * V_ + kp * KL, V_,
                           kp ? g_zero : (ba + n0),
                           g_pa4[kp] + n0, 5 * H_, KL);
        }
        grid_sync();

        // ---- phase 4: gates + state update + y ----
        if (blockIdx.x < B_)
            gate_work(blockIdx.x, t, Wo, bo, seq_lens, y, red);
        grid_sync();
    }
}

// ---------------------------------------------------------------------------
extern "C" void kernel_launch(void* const* d_in, const int* in_sizes, int n_in,
                              void* d_out, int out_size)
{
    const float* x      = (const float*)d_in[0];
    const float* visual = (const float*)d_in[1];
    const float* Wi     = (const float*)d_in[2];
    const float* bi     = (const float*)d_in[3];
    const float* Ws     = (const float*)d_in[4];
    const float* bs     = (const float*)d_in[5];
    const float* Wa     = (const float*)d_in[6];
    const float* ba     = (const float*)d_in[7];
    const float* Wv     = (const float*)d_in[8];
    const float* bv     = (const float*)d_in[9];
    const float* Wh     = (const float*)d_in[10];
    const float* bh     = (const float*)d_in[11];
    const float* Wp     = (const float*)d_in[12];
    const float* bp     = (const float*)d_in[13];
    const float* W0h    = (const float*)d_in[14];
    const float* b0h    = (const float*)d_in[15];
    const float* W0c    = (const float*)d_in[16];
    const float* b0c    = (const float*)d_in[17];
    const float* Wo     = (const float*)d_in[18];
    const float* bo     = (const float*)d_in[19];
    const int* ls_rois  = (const int*)d_in[20];
    const int* seq_lens = (const int*)d_in[21];
    float* y = (float*)d_out;

    float *p_mean, *p_h, *p_c, *p_va, *p_pi;
    cudaGetSymbolAddress((void**)&p_mean, g_mean);
    cudaGetSymbolAddress((void**)&p_h,    g_h);
    cudaGetSymbolAddress((void**)&p_c,    g_c);
    cudaGetSymbolAddress((void**)&p_va,   g_va);
    cudaGetSymbolAddress((void**)&p_pi,   g_pi);

    // ---- loop-invariant precompute ----
    mean_vis_kernel<<<B_, 256>>>(visual, ls_rois);
    gemm_nt_bias<<<dim3(H_ / 64, B_ / 64), 256>>>(p_mean, W0h, b0h, p_h, B_, H_, V_);
    gemm_nt_bias<<<dim3(H_ / 64, B_ / 64), 256>>>(p_mean, W0c, b0c, p_c, B_, H_, V_);
    gemm_nt_bias<<<dim3(A_ / 64, (B_ * NROI) / 64), 256>>>(visual, Wv, bv, p_va,
                                                           B_ * NROI, A_, V_);
    gemm_nt_bias<<<dim3((6 * H_) / 64, (B_ * T_) / 64), 256>>>(x, Wi, bi, p_pi,
                                                               B_ * T_, 6 * H_, DIN);

    // ---- entire recurrent loop: ONE persistent kernel ----
    loop_kernel<<<NB, 256>>>(Ws, bs, Wh, bh, Wa, ba, Wp, bp, Wo, bo,
                             visual, ls_rois, seq_lens, y);
}